// round 12
// baseline (speedup 1.0000x reference)
#include <cuda_runtime.h>
#include <cstdint>

#define GRID1   20
#define NCPAD   8192
#define CAP     16             // bucket capacity (overflow P ~ 2e-12)
#define KC      20             // register candidate cap (P(cnt>20) ~ 1e-9)
#define CSTRIDE 32
#define MAXM    8192
#define MAXN    8192
#define GBLK    128
#define TBLK    64
#define OWNER_INIT 0x7FFFFFFF

typedef unsigned long long u64;

// ---------------- device scratch (no allocations allowed) ----------------
__device__ int            g_cellcnt[NCPAD];          // zero-init; last block re-zeros
__device__ float4         g_bucket[NCPAD * CAP];     // (x,y,z,bitcast id)
__device__ uint4          g_row[MAXM];               // cnt | first 7 sorted candidates
__device__ unsigned short g_sorted[MAXM * CSTRIDE];  // overflow (pos >= 7)
__device__ int            g_owner[MAXN];             // packed (row<<5 | pos)
__device__ float          g_accN;                    // loss numerator
__device__ float          g_accK;                    // match count
__device__ volatile unsigned g_bcnt[4];              // zero-init; self-resetting
__device__ volatile unsigned g_bgen[4];              // monotonic generation

__device__ __forceinline__ int cell1(float x) {
    int c = (int)floorf(x * 0.2f);
    return min(max(c, 0), GRID1 - 1);
}

// Generation-based grid barrier; all GBLK blocks co-resident (128 <= 148 SMs).
__device__ __forceinline__ void gsync(int k) {
    __syncthreads();
    if (threadIdx.x == 0) {
        unsigned old = g_bgen[k];
        __threadfence();
        unsigned a = atomicAdd((unsigned*)&g_bcnt[k], 1u);
        if (a == GBLK - 1) {
            g_bcnt[k] = 0;
            __threadfence();
            atomicAdd((unsigned*)&g_bgen[k], 1u);
        } else {
            while (g_bgen[k] == old) { }
        }
    }
    __syncthreads();
    __threadfence();
}

// candidate p of a row given its packed uint4; own=true may use L1 (own writes)
__device__ __forceinline__ int cand_at(uint4 rv, int p, int row, bool own) {
    if (p < 7) {
        unsigned w = (p == 0) ? rv.x : (p < 3) ? rv.y : (p < 5) ? rv.z : rv.w;
        int sh = (p == 0) ? 16 : ((p & 1) ? 0 : 16);
        return (int)((w >> sh) & 0xFFFFu);
    }
    const unsigned short* q = &g_sorted[(size_t)row * CSTRIDE + p];
    return own ? (int)*q : (int)__ldcg(q);
}

__device__ __forceinline__ float sl1(float x) {
    float a = fabsf(x);
    return (a < 1.0f) ? 0.5f * a * a : a - 0.5f;
}

// Combined per-pair loss numerator. __noinline__ => ONE code object, so the
// claim-time value and any later displacement-time recomputation are bitwise
// identical and the accumulator telescopes exactly.
__device__ __noinline__ float pair_numer(const float* __restrict__ pp,
                                         const float* __restrict__ gg) {
    float p0 = __ldg(pp),     p1 = __ldg(pp + 1), p2 = __ldg(pp + 2);
    float p3 = __ldg(pp + 3), p4 = __ldg(pp + 4), p5 = __ldg(pp + 5);
    float p6 = __ldg(pp + 6);
    float g0 = __ldg(gg),     g1 = __ldg(gg + 1), g2 = __ldg(gg + 2);
    float g3 = __ldg(gg + 3), g4 = __ldg(gg + 4), g5 = __ldg(gg + 5);
    float g6 = __ldg(gg + 6);
    float sc = sl1(p0 - g0) + sl1(p1 - g1) + sl1(p2 - g2);
    float ss = sl1(p3 - g3) + sl1(p4 - g4) + sl1(p5 - g5);
    float dth = p6 - g6;
    dth = fmaf(-rintf(dth * 0.15915494309f), 6.283185307f, dth);
    float so = sl1(dth);                 // sl1(|.|) symmetric: wrap dir irrelevant
    float iw = fminf(p0 + p3 * 0.5f, g0 + g3 * 0.5f)
             - fmaxf(p0 - p3 * 0.5f, g0 - g3 * 0.5f);
    iw = fmaxf(iw, 0.0f);
    float ih = fminf(p1 + p4 * 0.5f, g1 + g4 * 0.5f)
             - fmaxf(p1 - p4 * 0.5f, g1 - g4 * 0.5f);
    ih = fmaxf(ih, 0.0f);
    float inter = iw * ih;
    float uni = p3 * p4 + g3 * g4 - inter;
    float si = 1.0f - inter / (uni + 1e-6f);
    return sc * (1.0f / 3.0f) + 0.5f * (ss * (1.0f / 3.0f) + so) + 2.0f * si;
}

__global__ void __launch_bounds__(TBLK)
fused_kernel(const float* __restrict__ pred, const float* __restrict__ gt,
             int m, int n, float* __restrict__ out) {
    __shared__ int s_last;
    int b = blockIdx.x, tid = threadIdx.x;
    int i = b * TBLK + tid;                 // one pred row AND one gt per thread

    // Hoist pred xyz loads: in flight during phase A + barrier.
    float px = 0.f, py = 0.f, pz = 0.f;
    bool rowv = (i < m);
    if (rowv) {
        px = __ldg(&pred[i * 7 + 0]);
        py = __ldg(&pred[i * 7 + 1]);
        pz = __ldg(&pred[i * 7 + 2]);
    }

    // ========== phase A: bucket build + owner/acc init (fully parallel) ====
    if (i == 0) g_accN = 0.0f;
    if (i == 1) g_accK = 0.0f;
    if (i < n) {
        g_owner[i] = OWNER_INIT;
        const float* g = gt + (size_t)i * 7;
        float gx = __ldg(g), gy = __ldg(g + 1), gz = __ldg(g + 2);
        int c = (cell1(gz) * GRID1 + cell1(gy)) * GRID1 + cell1(gx);
        int slot = atomicAdd(&g_cellcnt[c], 1);
        if (slot < CAP)
            g_bucket[c * CAP + slot] = make_float4(gx, gy, gz, __int_as_float(i));
    }
    gsync(0);

    // ========== phase B: query, z-plane batched, register min-sweep ========
    // Per-dim neighborhood [cell1(px-5), cell1(px+5)] spans <=3 consecutive
    // cells and is a superset (monotone f32 ops); exact dsq<25 test ->
    // identical candidate set to brute force. Entry0 loads speculative
    // (clamped in-bounds; used only when count>0). a[] holds the KC smallest
    // keys (fbits(dsq)<<32 | j) ascending via register min-sweep == exact
    // serial-argmin order (rounds 1-11).
    uint4 rv = make_uint4(0, 0, 0, 0);
    int   cnt = 0;
    if (rowv) {
        u64 a[KC];
        #pragma unroll
        for (int k = 0; k < KC; ++k) a[k] = ~0ull;
        int x0 = cell1(px - 5.0f), x1 = cell1(px + 5.0f);
        int y0 = cell1(py - 5.0f), y1 = cell1(py + 5.0f);
        int z0 = cell1(pz - 5.0f), z1 = cell1(pz + 5.0f);

        for (int zz = z0; zz <= z1; ++zz) {
            int    cc[9], ci[9];
            float4 v0[9];
            #pragma unroll
            for (int dy = 0; dy < 3; ++dy) {
                int yy = y0 + dy;
                #pragma unroll
                for (int dx = 0; dx < 3; ++dx) {
                    int k = dy * 3 + dx;
                    int xx = x0 + dx;
                    bool ok = (yy <= y1) && (xx <= x1);
                    int c = (zz * GRID1 + yy) * GRID1 + xx;
                    c = min(c, NCPAD - 1);           // clamp: always in-bounds
                    ci[k] = c;
                    cc[k] = ok ? __ldg(&g_cellcnt[c]) : 0;
                }
            }
            #pragma unroll
            for (int k = 0; k < 9; ++k) v0[k] = __ldg(&g_bucket[ci[k] * CAP]);

            #pragma unroll
            for (int k = 0; k < 9; ++k) {
                int c2 = min(cc[k], CAP);
                for (int t = 0; t < c2; ++t) {       // c2>1 rare (mean ~1)
                    float4 v = (t == 0) ? v0[k]
                                        : __ldg(&g_bucket[ci[k] * CAP + t]);
                    float dx = px - v.x, dy = py - v.y, dz = pz - v.z;
                    float d = fmaf(dx, dx, fmaf(dy, dy, dz * dz));
                    if (d < 25.0f) {
                        u64 key = ((u64)__float_as_uint(d) << 32)
                                | (unsigned)__float_as_int(v.w);
                        ++cnt;
                        #pragma unroll
                        for (int k2 = 0; k2 < KC; ++k2) {   // register min-sweep
                            u64 mn = min(a[k2], key);
                            key = a[k2] ^ key ^ mn;
                            a[k2] = mn;
                        }
                    }
                }
            }
        }
        cnt = min(cnt, KC);
        unsigned c7[7];
        #pragma unroll
        for (int k = 0; k < 7; ++k)
            c7[k] = (k < cnt) ? (unsigned)(a[k] & 0xFFFFu) : 0u;
        rv.x = (unsigned)cnt | (c7[0] << 16);
        rv.y = c7[1] | (c7[2] << 16);
        rv.z = c7[3] | (c7[4] << 16);
        rv.w = c7[5] | (c7[6] << 16);
        g_row[i] = rv;
        #pragma unroll
        for (int k = 7; k < KC; ++k)
            if (k < cnt)
                g_sorted[(size_t)i * CSTRIDE + k] =
                    (unsigned short)(a[k] & 0xFFFFu);
    }
    __threadfence();   // release g_row/g_sorted before owner atomics

    // ========== phase C: eager-chain matcher + FUSED loss accounting =======
    // owner[j] = min packed (row<<5|pos) ever proposed (atomicMin, monotone).
    // Packed lexicographic order == row priority; fixed point == sequential
    // greedy (rounds 3-11). NEW: the atomic RMW chain on owner[j] linearizes
    // loss deltas — claim-on-empty adds (numer,+1); displacement adds
    // numer_new - numer_old (count unchanged; old pair's value recomputed
    // bitwise-identically by pair_numer). Sum telescopes to the fixed point.
    if (rowv) {
        int cur = i, p = 0, ccnt = cnt;
        uint4 crv = rv;
        bool own = true;
        while (p < ccnt) {
            int j = cand_at(crv, p, cur, own);
            int my = (cur << 5) | p;
            int old = atomicMin(&g_owner[j], my);
            if (old < my) { ++p; continue; }     // better owner: advance
            float Lnew = pair_numer(pred + (size_t)cur * 7, gt + (size_t)j * 7);
            if (old == OWNER_INIT) {             // claimed empty slot: done
                atomicAdd(&g_accN, Lnew);
                atomicAdd(&g_accK, 1.0f);
                break;
            }
            // displaced row old>>5: swap its contribution for ours, walk on
            float Lold = pair_numer(pred + (size_t)(old >> 5) * 7,
                                    gt + (size_t)j * 7);
            atomicAdd(&g_accN, Lnew - Lold);
            cur = old >> 5;
            p = (old & 31) + 1;
            crv = __ldcg(&g_row[cur]);
            ccnt = (int)(crv.x & 0xFFFFu);
            own = false;
        }
    }

    // ========== finalize: arrive-only; last block writes out + cleans up ===
    __syncthreads();
    if (tid == 0) {
        __threadfence();                         // order REDs before arrival
        unsigned a = atomicAdd((unsigned*)&g_bcnt[2], 1u);
        s_last = (a == GBLK - 1) ? 1 : 0;
        if (s_last) g_bcnt[2] = 0;
    }
    __syncthreads();
    if (s_last) {
        if (tid == 0) {
            float N = atomicAdd(&g_accN, 0.0f);
            float K = atomicAdd(&g_accK, 0.0f);
            out[0] = N / fmaxf(K, 1.0f);
        }
        for (int c = tid; c < NCPAD; c += TBLK)  // zero-state for next replay
            g_cellcnt[c] = 0;
    }
}

// ---------------- launch ----------------
extern "C" void kernel_launch(void* const* d_in, const int* in_sizes, int n_in,
                              void* d_out, int out_size) {
    const float* pred = (const float*)d_in[0];
    const float* gt   = (const float*)d_in[1];
    int m = in_sizes[0] / 7;
    int n = in_sizes[1] / 7;
    fused_kernel<<<GBLK, TBLK>>>(pred, gt, m, n, (float*)d_out);
}

// round 13
// speedup vs baseline: 1.2897x; 1.2897x over previous
#include <cuda_runtime.h>
#include <cstdint>

#define GRID1   20
#define NCPAD   8192
#define CAP     16             // bucket capacity (overflow P ~ 2e-12)
#define KC      20             // merged candidate cap (P(cnt>20) ~ 1e-9)
#define KC_L    12             // per-quad-thread local cap
#define STAGE   24             // per-row smem staging slots
#define CSTRIDE 32
#define MAXM    8192
#define MAXN    8192
#define GBLK    128
#define TBLK    256
#define ROWS_PB (TBLK / 4)     // 64 rows per block
#define OWNER_INIT 0x7FFFFFFF

typedef unsigned long long u64;

// ---------------- device scratch (no allocations allowed) ----------------
__device__ int            g_cellcnt[NCPAD];          // zero-init; phase D re-zeros
__device__ float4         g_bucket[NCPAD * CAP];     // (x,y,z,bitcast id)
__device__ uint4          g_row[MAXM];               // cnt | first 7 sorted candidates
__device__ unsigned short g_sorted[MAXM * CSTRIDE];  // overflow (pos >= 7)
__device__ int            g_owner[MAXN];             // packed (row<<5 | pos)
__device__ float          g_acc[5];
__device__ volatile unsigned g_bcnt[4];              // zero-init; self-resetting
__device__ volatile unsigned g_bgen[4];              // monotonic generation

__device__ __forceinline__ int cell1(float x) {
    int c = (int)floorf(x * 0.2f);
    return min(max(c, 0), GRID1 - 1);
}

// Generation-based grid barrier; all GBLK blocks co-resident (128 <= 148 SMs).
__device__ __forceinline__ void gsync(int k) {
    __syncthreads();
    if (threadIdx.x == 0) {
        unsigned old = g_bgen[k];
        __threadfence();
        unsigned a = atomicAdd((unsigned*)&g_bcnt[k], 1u);
        if (a == GBLK - 1) {
            g_bcnt[k] = 0;
            __threadfence();
            atomicAdd((unsigned*)&g_bgen[k], 1u);
        } else {
            while (g_bgen[k] == old) { }
        }
    }
    __syncthreads();
    __threadfence();
}

// candidate p of a row given its packed uint4; own=true may use L1 (own writes)
__device__ __forceinline__ int cand_at(uint4 rv, int p, int row, bool own) {
    if (p < 7) {
        unsigned w = (p == 0) ? rv.x : (p < 3) ? rv.y : (p < 5) ? rv.z : rv.w;
        int sh = (p == 0) ? 16 : ((p & 1) ? 0 : 16);
        return (int)((w >> sh) & 0xFFFFu);
    }
    const unsigned short* q = &g_sorted[(size_t)row * CSTRIDE + p];
    return own ? (int)*q : (int)__ldcg(q);
}

__device__ __forceinline__ float sl1(float x) {
    float a = fabsf(x);
    return (a < 1.0f) ? 0.5f * a * a : a - 0.5f;
}

__global__ void __launch_bounds__(TBLK)
fused_kernel(const float* __restrict__ pred, const float* __restrict__ gt,
             int m, int n, float* __restrict__ out) {
    __shared__ u64 s_keys[ROWS_PB * STAGE];     // 12 KB staging
    __shared__ int s_cnt[ROWS_PB];
    int b = blockIdx.x, tid = threadIdx.x;
    int lane = tid & 31;
    int gtid = b * TBLK + tid;
    int row  = gtid >> 2;                        // quad: 4 threads per pred row
    int q    = tid & 3;
    int lrow = tid >> 2;                         // row index within block
    bool rowv = (row < m);
    bool lead = (q == 0) && rowv;

    if (tid < ROWS_PB) s_cnt[tid] = 0;

    // All quad lanes load their row's pred xyz (same line; broadcast).
    float px = 0.f, py = 0.f, pz = 0.f;
    if (rowv) {
        px = __ldg(&pred[row * 7 + 0]);
        py = __ldg(&pred[row * 7 + 1]);
        pz = __ldg(&pred[row * 7 + 2]);
    }

    // ========== phase A: bucket build + owner/acc init (fully parallel) ====
    if (gtid < 5) g_acc[gtid] = 0.0f;
    if (gtid < n) {
        g_owner[gtid] = OWNER_INIT;
        const float* g = gt + (size_t)gtid * 7;
        float gx = __ldg(g), gy = __ldg(g + 1), gz = __ldg(g + 2);
        int c = (cell1(gz) * GRID1 + cell1(gy)) * GRID1 + cell1(gx);
        int slot = atomicAdd(&g_cellcnt[c], 1);
        if (slot < CAP)
            g_bucket[c * CAP + slot] = make_float4(gx, gy, gz,
                                                   __int_as_float(gtid));
    }
    gsync(0);

    // ========== phase B: quad-parallel query =================================
    // 27 neighbor cells split 7-per-quad-thread (k = q + 4t, k<27): union ==
    // full [cell1(px-5),cell1(px+5)]^3 superset (monotone f32 ops); exact
    // dsq<25 test -> identical candidate set to brute force (rounds 1-12).
    // Each thread min-sweeps hits into a local sorted list, stages to SMEM;
    // the leader merges via the same min-sweep. Keys (fbits(dsq)<<32 | j) are
    // unique, so the sorted merge erases staging-order races -> deterministic,
    // exact serial-argmin order.
    uint4 rv = make_uint4(0, 0, 0, 0);
    int   cnt = 0;
    if (rowv) {
        int x0 = cell1(px - 5.0f), x1 = cell1(px + 5.0f);
        int y0 = cell1(py - 5.0f), y1 = cell1(py + 5.0f);
        int z0 = cell1(pz - 5.0f), z1 = cell1(pz + 5.0f);

        u64 loc[KC_L];
        #pragma unroll
        for (int k = 0; k < KC_L; ++k) loc[k] = ~0ull;
        int lc = 0;

        int    cc[7], ci[7];
        float4 v0[7];
        #pragma unroll
        for (int t = 0; t < 7; ++t) {
            int k = q + 4 * t;
            int zz = z0 + k / 9, yy = y0 + (k % 9) / 3, xx = x0 + k % 3;
            bool ok = (k < 27) && (zz <= z1) && (yy <= y1) && (xx <= x1);
            int c = (zz * GRID1 + yy) * GRID1 + xx;
            c = min(max(c, 0), NCPAD - 1);       // clamp: always in-bounds
            ci[t] = c;
            cc[t] = ok ? __ldg(&g_cellcnt[c]) : 0;
        }
        #pragma unroll
        for (int t = 0; t < 7; ++t) v0[t] = __ldg(&g_bucket[ci[t] * CAP]);

        #pragma unroll
        for (int t = 0; t < 7; ++t) {
            int c2 = min(cc[t], CAP);
            for (int e = 0; e < c2; ++e) {       // c2>1 rare (mean ~1)
                float4 v = (e == 0) ? v0[t] : __ldg(&g_bucket[ci[t] * CAP + e]);
                float dx = px - v.x, dy = py - v.y, dz = pz - v.z;
                float d = fmaf(dx, dx, fmaf(dy, dy, dz * dz));
                if (d < 25.0f) {
                    u64 key = ((u64)__float_as_uint(d) << 32)
                            | (unsigned)__float_as_int(v.w);
                    ++lc;
                    #pragma unroll
                    for (int k2 = 0; k2 < KC_L; ++k2) {   // register min-sweep
                        u64 mn = min(loc[k2], key);
                        key = loc[k2] ^ key ^ mn;
                        loc[k2] = mn;
                    }
                }
            }
        }
        lc = min(lc, KC_L);
        int pos = atomicAdd(&s_cnt[lrow], lc);
        #pragma unroll
        for (int e = 0; e < KC_L; ++e)
            if (e < lc && pos + e < STAGE)
                s_keys[lrow * STAGE + pos + e] = loc[e];
    }
    __syncwarp(0xFFFFFFFFu);                     // quad is intra-warp

    if (lead) {
        int tot = min(s_cnt[lrow], STAGE);
        u64 a[KC];
        #pragma unroll
        for (int k = 0; k < KC; ++k) a[k] = ~0ull;
        for (int e = 0; e < tot; ++e) {
            u64 key = s_keys[lrow * STAGE + e];
            #pragma unroll
            for (int k2 = 0; k2 < KC; ++k2) {    // merge min-sweep
                u64 mn = min(a[k2], key);
                key = a[k2] ^ key ^ mn;
                a[k2] = mn;
            }
        }
        cnt = min(tot, KC);
        unsigned c7[7];
        #pragma unroll
        for (int k = 0; k < 7; ++k)
            c7[k] = (k < cnt) ? (unsigned)(a[k] & 0xFFFFu) : 0u;
        rv.x = (unsigned)cnt | (c7[0] << 16);
        rv.y = c7[1] | (c7[2] << 16);
        rv.z = c7[3] | (c7[4] << 16);
        rv.w = c7[5] | (c7[6] << 16);
        g_row[row] = rv;
        #pragma unroll
        for (int k = 7; k < KC; ++k)
            if (k < cnt)
                g_sorted[(size_t)row * CSTRIDE + k] =
                    (unsigned short)(a[k] & 0xFFFFu);
    }
    __threadfence();   // release g_row/g_sorted before owner atomics

    // ========== phase C: eager-chain greedy matcher (leaders only) =========
    // owner[j] = min packed (row<<5|pos) ever proposed (atomicMin, monotone).
    // Packed lexicographic order == row priority. On displacement, the winner
    // continues the displaced row's walk (position from the returned value).
    // Fixed point is order-independent == sequential greedy (rounds 3-12).
    if (lead) {
        int cur = row, p = 0, ccnt = cnt;
        uint4 crv = rv;
        bool own = true;
        while (p < ccnt) {
            int j = cand_at(crv, p, cur, own);
            int my = (cur << 5) | p;
            int old = atomicMin(&g_owner[j], my);
            if (old < my) { ++p; continue; }     // better owner: advance
            if (old == OWNER_INIT) break;        // parked in empty slot: done
            cur = old >> 5;                      // continue displaced row
            p = (old & 31) + 1;
            crv = __ldcg(&g_row[cur]);
            ccnt = (int)(crv.x & 0xFFFFu);
            own = false;
        }
    }
    gsync(1);

    // ========== phase D: gt-side loss (owner[j]>>5 IS the matched row) =====
    // At fixed point each row owns <=1 gt, so iterating gts (one per quad
    // leader, gt index == row) enumerates exactly the matched pairs.
    if (gtid < NCPAD) g_cellcnt[gtid] = 0;       // zero-state for next replay

    float sc = 0.f, ss = 0.f, so = 0.f, si = 0.f, cf = 0.f;
    if (lead && row < n) {
        int v = __ldcg(&g_owner[row]);           // atomics live in L2
        if (v != OWNER_INIT) {
            int r = v >> 5;                      // matched pred row
            cf = 1.0f;
            const float* pp = pred + (size_t)r * 7;
            const float* gg = gt + (size_t)row * 7;
            float p0 = __ldg(pp),     p1 = __ldg(pp + 1), p2 = __ldg(pp + 2);
            float p3 = __ldg(pp + 3), p4 = __ldg(pp + 4), p5 = __ldg(pp + 5);
            float p6 = __ldg(pp + 6);
            float g0 = __ldg(gg),     g1 = __ldg(gg + 1), g2 = __ldg(gg + 2);
            float g3 = __ldg(gg + 3), g4 = __ldg(gg + 4), g5 = __ldg(gg + 5);
            float g6 = __ldg(gg + 6);
            sc = sl1(p0 - g0) + sl1(p1 - g1) + sl1(p2 - g2);
            ss = sl1(p3 - g3) + sl1(p4 - g4) + sl1(p5 - g5);
            float dth = p6 - g6;
            dth = fmaf(-rintf(dth * 0.15915494309f), 6.283185307f, dth);
            so = sl1(dth);                       // sl1(|.|) symmetric
            float iw = fminf(p0 + p3 * 0.5f, g0 + g3 * 0.5f)
                     - fmaxf(p0 - p3 * 0.5f, g0 - g3 * 0.5f);
            iw = fmaxf(iw, 0.0f);
            float ih = fminf(p1 + p4 * 0.5f, g1 + g4 * 0.5f)
                     - fmaxf(p1 - p4 * 0.5f, g1 - g4 * 0.5f);
            ih = fmaxf(ih, 0.0f);
            float inter = iw * ih;
            float uni = p3 * p4 + g3 * g4 - inter;
            si = 1.0f - inter / (uni + 1e-6f);
        }
    }
    #pragma unroll
    for (int o = 16; o; o >>= 1) {
        sc += __shfl_down_sync(0xFFFFFFFFu, sc, o);
        ss += __shfl_down_sync(0xFFFFFFFFu, ss, o);
        so += __shfl_down_sync(0xFFFFFFFFu, so, o);
        si += __shfl_down_sync(0xFFFFFFFFu, si, o);
        cf += __shfl_down_sync(0xFFFFFFFFu, cf, o);
    }
    if (lane == 0 && cf != 0.0f) {
        atomicAdd(&g_acc[0], sc);
        atomicAdd(&g_acc[1], ss);
        atomicAdd(&g_acc[2], so);
        atomicAdd(&g_acc[3], si);
        atomicAdd(&g_acc[4], cf);
    }

    // ========== finalize: arrive-only; last arriver writes out =============
    __syncthreads();
    if (tid == 0) {
        __threadfence();
        unsigned a = atomicAdd((unsigned*)&g_bcnt[2], 1u);
        if (a == GBLK - 1) {
            g_bcnt[2] = 0;
            float a0 = atomicAdd(&g_acc[0], 0.0f);
            float a1 = atomicAdd(&g_acc[1], 0.0f);
            float a2 = atomicAdd(&g_acc[2], 0.0f);
            float a3 = atomicAdd(&g_acc[3], 0.0f);
            float a4 = atomicAdd(&g_acc[4], 0.0f);
            float k  = fmaxf(a4, 1.0f);
            out[0] = a0 / (3.0f * k) + 0.5f * (a1 / (3.0f * k) + a2 / k)
                   + 2.0f * (a3 / k);
        }
    }
}

// ---------------- launch ----------------
extern "C" void kernel_launch(void* const* d_in, const int* in_sizes, int n_in,
                              void* d_out, int out_size) {
    const float* pred = (const float*)d_in[0];
    const float* gt   = (const float*)d_in[1];
    int m = in_sizes[0] / 7;
    int n = in_sizes[1] / 7;
    fused_kernel<<<GBLK, TBLK>>>(pred, gt, m, n, (float*)d_out);
}